// round 7
// baseline (speedup 1.0000x reference)
#include <cuda_runtime.h>
#include <cuda_bf16.h>

// Sorted segment-sum: values (N, 256) fp32, segment_ids (N) sorted int32 in [0, B),
// out (B, 256) fp32.  DRAM-bound streaming kernel. Warp-per-row layout with
// Blackwell 256-bit streaming loads (LDG.E.256): one instruction = one full
// 1KB row per warp. Uniform-segment blocks (~87%) take a check-free path.

#define C_COLS   256
#define RPB      256     // rows per block (divides N exactly)
#define UNR      4       // rows in flight per warp per iteration

// 256-bit streaming load (sm_100a+/sm_103a, PTX ISA 8.8).
__device__ __forceinline__ void ldcs_v8(const float* p, float* r) {
    asm volatile("ld.global.cs.v8.f32 {%0,%1,%2,%3,%4,%5,%6,%7}, [%8];"
                 : "=f"(r[0]), "=f"(r[1]), "=f"(r[2]), "=f"(r[3]),
                   "=f"(r[4]), "=f"(r[5]), "=f"(r[6]), "=f"(r[7])
                 : "l"(p));
}

// Vectorized fire-and-forget global reduction: one REDG.128.
__device__ __forceinline__ void red_add_v4(float* addr,
                                           float a, float b, float c, float d) {
    asm volatile("red.global.add.v4.f32 [%0], {%1, %2, %3, %4};"
                 :: "l"(addr), "f"(a), "f"(b), "f"(c), "f"(d)
                 : "memory");
}

__global__ __launch_bounds__(256)
void segsum_kernel(const float* __restrict__ vals,
                   const int*   __restrict__ seg,
                   float*       __restrict__ out,
                   int n)
{
    const int lane = threadIdx.x;   // 0..31: 32B (8-float) chunk of the row
    const int w    = threadIdx.y;   // 0..7 : warp id

    const int row0 = blockIdx.x * RPB;
    int rows = n - row0;
    if (rows > RPB) rows = RPB;

    float acc[8];
    #pragma unroll
    for (int i = 0; i < 8; i++) acc[i] = 0.0f;

    const int colf = lane * 8;      // float offset within row

    if (rows == RPB) {
        const int s_first = __ldg(&seg[row0]);
        const int s_last  = __ldg(&seg[row0 + RPB - 1]);

        if (s_first == s_last) {
            // ---- uniform-segment fast path: pure streaming accumulate ----
            #pragma unroll 1
            for (int r = 0; r < RPB; r += 8 * UNR) {
                float buf[UNR][8];
                #pragma unroll
                for (int u = 0; u < UNR; u++) {
                    const int row = row0 + r + w * UNR + u;
                    ldcs_v8(vals + (size_t)row * C_COLS + colf, buf[u]);
                }
                #pragma unroll
                for (int u = 0; u < UNR; u++)
                    #pragma unroll
                    for (int i = 0; i < 8; i++)
                        acc[i] += buf[u][i];
            }
            float* o = out + (size_t)s_first * C_COLS + colf;
            red_add_v4(o,     acc[0], acc[1], acc[2], acc[3]);
            red_add_v4(o + 4, acc[4], acc[5], acc[6], acc[7]);
            return;
        }

        // ---- boundary block: per-row segment tracking (warp-sorted order) ----
        int cur = __ldg(&seg[row0 + w * UNR]);
        #pragma unroll 1
        for (int r = 0; r < RPB; r += 8 * UNR) {
            int sb[UNR];
            #pragma unroll
            for (int u = 0; u < UNR; u++)
                sb[u] = __ldg(&seg[row0 + r + w * UNR + u]);

            float buf[UNR][8];
            #pragma unroll
            for (int u = 0; u < UNR; u++) {
                const int row = row0 + r + w * UNR + u;
                ldcs_v8(vals + (size_t)row * C_COLS + colf, buf[u]);
            }

            #pragma unroll
            for (int u = 0; u < UNR; u++) {
                if (sb[u] != cur) {
                    float* o = out + (size_t)cur * C_COLS + colf;
                    red_add_v4(o,     acc[0], acc[1], acc[2], acc[3]);
                    red_add_v4(o + 4, acc[4], acc[5], acc[6], acc[7]);
                    #pragma unroll
                    for (int i = 0; i < 8; i++) acc[i] = 0.0f;
                    cur = sb[u];
                }
                #pragma unroll
                for (int i = 0; i < 8; i++)
                    acc[i] += buf[u][i];
            }
        }
        float* o = out + (size_t)cur * C_COLS + colf;
        red_add_v4(o,     acc[0], acc[1], acc[2], acc[3]);
        red_add_v4(o + 4, acc[4], acc[5], acc[6], acc[7]);
        return;
    }

    // ---- ragged tail block (n not multiple of RPB) ----
    if (w >= rows) return;
    int cur = __ldg(&seg[row0 + w]);
    for (int row = row0 + w; row < row0 + rows; row += 8) {
        float buf[8];
        ldcs_v8(vals + (size_t)row * C_COLS + colf, buf);
        const int s = __ldg(&seg[row]);
        if (s != cur) {
            float* o = out + (size_t)cur * C_COLS + colf;
            red_add_v4(o,     acc[0], acc[1], acc[2], acc[3]);
            red_add_v4(o + 4, acc[4], acc[5], acc[6], acc[7]);
            #pragma unroll
            for (int i = 0; i < 8; i++) acc[i] = 0.0f;
            cur = s;
        }
        #pragma unroll
        for (int i = 0; i < 8; i++)
            acc[i] += buf[i];
    }
    float* o = out + (size_t)cur * C_COLS + colf;
    red_add_v4(o,     acc[0], acc[1], acc[2], acc[3]);
    red_add_v4(o + 4, acc[4], acc[5], acc[6], acc[7]);
}

extern "C" void kernel_launch(void* const* d_in, const int* in_sizes, int n_in,
                              void* d_out, int out_size)
{
    const float* values = (const float*)d_in[0];
    const int*   segids = (const int*)d_in[1];
    float* out = (float*)d_out;

    const int n = in_sizes[1];   // number of rows

    // Output is poisoned; zero it (graph-capturable memset node), flushes
    // accumulate on top.
    cudaMemsetAsync(out, 0, (size_t)out_size * sizeof(float));

    dim3 block(32, 8);
    int grid = (n + RPB - 1) / RPB;
    segsum_kernel<<<grid, block>>>(values, segids, out, n);
}

// round 8
// speedup vs baseline: 1.0101x; 1.0101x over previous
#include <cuda_runtime.h>
#include <cuda_bf16.h>

// Sorted segment-sum: values (N, 256) fp32, segment_ids (N) sorted int32 in [0, B),
// out (B, 256) fp32.  DRAM-bound streaming kernel. Warp-per-row layout with
// Blackwell 256-bit streaming loads (LDG.E.256): one instruction = one full
// 1KB row per warp. Uniform-segment blocks (~87%) take a check-free path.

#define C_COLS   256
#define RPB      256     // rows per block (divides N exactly)
#define UNR      4       // rows in flight per warp per iteration

// 256-bit streaming load (sm_100a+/sm_103a, PTX ISA 8.8).
__device__ __forceinline__ void ldcs_v8(const float* p, float* r) {
    asm volatile("ld.global.cs.v8.f32 {%0,%1,%2,%3,%4,%5,%6,%7}, [%8];"
                 : "=f"(r[0]), "=f"(r[1]), "=f"(r[2]), "=f"(r[3]),
                   "=f"(r[4]), "=f"(r[5]), "=f"(r[6]), "=f"(r[7])
                 : "l"(p));
}

// Vectorized fire-and-forget global reduction: one REDG.128.
__device__ __forceinline__ void red_add_v4(float* addr,
                                           float a, float b, float c, float d) {
    asm volatile("red.global.add.v4.f32 [%0], {%1, %2, %3, %4};"
                 :: "l"(addr), "f"(a), "f"(b), "f"(c), "f"(d)
                 : "memory");
}

__global__ __launch_bounds__(256)
void segsum_kernel(const float* __restrict__ vals,
                   const int*   __restrict__ seg,
                   float*       __restrict__ out,
                   int n)
{
    const int lane = threadIdx.x;   // 0..31: 32B (8-float) chunk of the row
    const int w    = threadIdx.y;   // 0..7 : warp id

    const int row0 = blockIdx.x * RPB;
    int rows = n - row0;
    if (rows > RPB) rows = RPB;

    float acc[8];
    #pragma unroll
    for (int i = 0; i < 8; i++) acc[i] = 0.0f;

    const int colf = lane * 8;      // float offset within row

    if (rows == RPB) {
        const int s_first = __ldg(&seg[row0]);
        const int s_last  = __ldg(&seg[row0 + RPB - 1]);

        if (s_first == s_last) {
            // ---- uniform-segment fast path: pure streaming accumulate ----
            #pragma unroll 1
            for (int r = 0; r < RPB; r += 8 * UNR) {
                float buf[UNR][8];
                #pragma unroll
                for (int u = 0; u < UNR; u++) {
                    const int row = row0 + r + w * UNR + u;
                    ldcs_v8(vals + (size_t)row * C_COLS + colf, buf[u]);
                }
                #pragma unroll
                for (int u = 0; u < UNR; u++)
                    #pragma unroll
                    for (int i = 0; i < 8; i++)
                        acc[i] += buf[u][i];
            }
            float* o = out + (size_t)s_first * C_COLS + colf;
            red_add_v4(o,     acc[0], acc[1], acc[2], acc[3]);
            red_add_v4(o + 4, acc[4], acc[5], acc[6], acc[7]);
            return;
        }

        // ---- boundary block: per-row segment tracking (warp-sorted order) ----
        int cur = __ldg(&seg[row0 + w * UNR]);
        #pragma unroll 1
        for (int r = 0; r < RPB; r += 8 * UNR) {
            int sb[UNR];
            #pragma unroll
            for (int u = 0; u < UNR; u++)
                sb[u] = __ldg(&seg[row0 + r + w * UNR + u]);

            float buf[UNR][8];
            #pragma unroll
            for (int u = 0; u < UNR; u++) {
                const int row = row0 + r + w * UNR + u;
                ldcs_v8(vals + (size_t)row * C_COLS + colf, buf[u]);
            }

            #pragma unroll
            for (int u = 0; u < UNR; u++) {
                if (sb[u] != cur) {
                    float* o = out + (size_t)cur * C_COLS + colf;
                    red_add_v4(o,     acc[0], acc[1], acc[2], acc[3]);
                    red_add_v4(o + 4, acc[4], acc[5], acc[6], acc[7]);
                    #pragma unroll
                    for (int i = 0; i < 8; i++) acc[i] = 0.0f;
                    cur = sb[u];
                }
                #pragma unroll
                for (int i = 0; i < 8; i++)
                    acc[i] += buf[u][i];
            }
        }
        float* o = out + (size_t)cur * C_COLS + colf;
        red_add_v4(o,     acc[0], acc[1], acc[2], acc[3]);
        red_add_v4(o + 4, acc[4], acc[5], acc[6], acc[7]);
        return;
    }

    // ---- ragged tail block (n not multiple of RPB) ----
    if (w >= rows) return;
    int cur = __ldg(&seg[row0 + w]);
    for (int row = row0 + w; row < row0 + rows; row += 8) {
        float buf[8];
        ldcs_v8(vals + (size_t)row * C_COLS + colf, buf);
        const int s = __ldg(&seg[row]);
        if (s != cur) {
            float* o = out + (size_t)cur * C_COLS + colf;
            red_add_v4(o,     acc[0], acc[1], acc[2], acc[3]);
            red_add_v4(o + 4, acc[4], acc[5], acc[6], acc[7]);
            #pragma unroll
            for (int i = 0; i < 8; i++) acc[i] = 0.0f;
            cur = s;
        }
        #pragma unroll
        for (int i = 0; i < 8; i++)
            acc[i] += buf[i];
    }
    float* o = out + (size_t)cur * C_COLS + colf;
    red_add_v4(o,     acc[0], acc[1], acc[2], acc[3]);
    red_add_v4(o + 4, acc[4], acc[5], acc[6], acc[7]);
}

extern "C" void kernel_launch(void* const* d_in, const int* in_sizes, int n_in,
                              void* d_out, int out_size)
{
    const float* values = (const float*)d_in[0];
    const int*   segids = (const int*)d_in[1];
    float* out = (float*)d_out;

    const int n = in_sizes[1];   // number of rows

    // Output is poisoned; zero it (graph-capturable memset node), flushes
    // accumulate on top.
    cudaMemsetAsync(out, 0, (size_t)out_size * sizeof(float));

    dim3 block(32, 8);
    int grid = (n + RPB - 1) / RPB;
    segsum_kernel<<<grid, block>>>(values, segids, out, n);
}

// round 9
// speedup vs baseline: 1.0383x; 1.0279x over previous
#include <cuda_runtime.h>
#include <cuda_bf16.h>

// Sorted segment-sum: values (N, 256) fp32, segment_ids (N) sorted int32 in [0, B),
// out (B, 256) fp32.  DRAM-bound streaming kernel: many small self-balancing
// blocks (RPB=128 -> short finish tail), register accumulation, rare
// vectorized-REDG flushes. Blocks entirely inside one segment (~94% at avg
// seglen 2048) take a check-free pure-streaming path.

#define C_COLS   256
#define CV       64      // float4 per row (256 floats)
#define RPB      128     // rows per block (divides N exactly -> no ragged tail)
#define UNR      8       // independent row-loads per thread per iteration (MLP)

// Vectorized fire-and-forget global reduction: one REDG.128.
__device__ __forceinline__ void red_add_v4(float* addr, float4 v) {
    asm volatile("red.global.add.v4.f32 [%0], {%1, %2, %3, %4};"
                 :: "l"(addr), "f"(v.x), "f"(v.y), "f"(v.z), "f"(v.w)
                 : "memory");
}

__global__ __launch_bounds__(256)
void segsum_kernel(const float4* __restrict__ vals,
                   const int*    __restrict__ seg,
                   float*        __restrict__ out,
                   int n)
{
    const int col = threadIdx.x;   // 0..63  (float4 column group)
    const int y   = threadIdx.y;   // 0..3   (row sub-stream)

    const int row0 = blockIdx.x * RPB;
    int rows = n - row0;
    if (rows > RPB) rows = RPB;

    float4 acc = make_float4(0.f, 0.f, 0.f, 0.f);

    if (rows == RPB) {
        const int s_first = __ldg(&seg[row0]);
        const int s_last  = __ldg(&seg[row0 + RPB - 1]);

        if (s_first == s_last) {
            // ---- uniform-segment fast path: pure streaming accumulate ----
            #pragma unroll 1
            for (int r = y; r < RPB; r += 4 * UNR) {
                float4 buf[UNR];
                #pragma unroll
                for (int u = 0; u < UNR; u++)
                    buf[u] = __ldcs(&vals[(size_t)(row0 + r + 4 * u) * CV + col]);
                #pragma unroll
                for (int u = 0; u < UNR; u++) {
                    acc.x += buf[u].x;
                    acc.y += buf[u].y;
                    acc.z += buf[u].z;
                    acc.w += buf[u].w;
                }
            }
            red_add_v4(out + (size_t)s_first * C_COLS + col * 4, acc);
            return;
        }

        // ---- boundary block: per-row segment tracking ----
        int cur = __ldg(&seg[row0 + y]);
        #pragma unroll 1
        for (int r = y; r < RPB; r += 4 * UNR) {
            int sb[UNR];
            #pragma unroll
            for (int u = 0; u < UNR; u++)
                sb[u] = __ldg(&seg[row0 + r + 4 * u]);
            float4 buf[UNR];
            #pragma unroll
            for (int u = 0; u < UNR; u++)
                buf[u] = __ldcs(&vals[(size_t)(row0 + r + 4 * u) * CV + col]);

            #pragma unroll
            for (int u = 0; u < UNR; u++) {
                if (sb[u] != cur) {
                    red_add_v4(out + (size_t)cur * C_COLS + col * 4, acc);
                    acc = make_float4(0.f, 0.f, 0.f, 0.f);
                    cur = sb[u];
                }
                acc.x += buf[u].x;
                acc.y += buf[u].y;
                acc.z += buf[u].z;
                acc.w += buf[u].w;
            }
        }
        red_add_v4(out + (size_t)cur * C_COLS + col * 4, acc);
        return;
    }

    // ---- ragged tail block (n not multiple of RPB) ----
    int cur = (y < rows) ? __ldg(&seg[row0 + y]) : -1;
    for (int r = y; r < rows; r += 4) {
        float4 v = __ldcs(&vals[(size_t)(row0 + r) * CV + col]);
        const int s = __ldg(&seg[row0 + r]);
        if (s != cur) {
            red_add_v4(out + (size_t)cur * C_COLS + col * 4, acc);
            acc = make_float4(0.f, 0.f, 0.f, 0.f);
            cur = s;
        }
        acc.x += v.x;
        acc.y += v.y;
        acc.z += v.z;
        acc.w += v.w;
    }
    if (cur >= 0)
        red_add_v4(out + (size_t)cur * C_COLS + col * 4, acc);
}

extern "C" void kernel_launch(void* const* d_in, const int* in_sizes, int n_in,
                              void* d_out, int out_size)
{
    const float* values = (const float*)d_in[0];
    const int*   segids = (const int*)d_in[1];
    float* out = (float*)d_out;

    const int n = in_sizes[1];   // number of rows

    // Output is poisoned; zero it (graph-capturable memset node), flushes
    // accumulate on top.
    cudaMemsetAsync(out, 0, (size_t)out_size * sizeof(float));

    dim3 block(64, 4);
    int grid = (n + RPB - 1) / RPB;
    segsum_kernel<<<grid, block>>>((const float4*)values, segids, out, n);
}